// round 3
// baseline (speedup 1.0000x reference)
#include <cuda_runtime.h>
#include <cstdint>

#define Bv 128
#define Sv 1024
#define Fv 512
#define Hv 128
#define G3 (3*Hv)

typedef unsigned long long ull;

// ---------------- scratch (static device arrays; no allocation) ----------------
__device__ float g_xg[(size_t)Bv * Sv * G3];     // xg0, later reused for xg1
__device__ float g_proj[(size_t)Bv * Sv * Hv];   // proj, later reused for h1
__device__ int   g_len[Bv];
__device__ int   g_rank[Bv];

// ---------------- f32x2 helpers (Blackwell packed fp32) ----------------
static __device__ __forceinline__ ull pk2(float x, float y) {
    ull r;
    asm("mov.b64 %0, {%1, %2};" : "=l"(r) : "f"(x), "f"(y));
    return r;
}
static __device__ __forceinline__ ull dup2(float x) {
    ull r;
    asm("mov.b64 %0, {%1, %1};" : "=l"(r) : "f"(x));
    return r;
}
static __device__ __forceinline__ void fma2p(ull &d, ull a, ull b) {
    asm("fma.rn.f32x2 %0, %1, %2, %0;" : "+l"(d) : "l"(a), "l"(b));
}
static __device__ __forceinline__ ull add2(ull a, ull b) {
    ull r;
    asm("add.rn.f32x2 %0, %1, %2;" : "=l"(r) : "l"(a), "l"(b));
    return r;
}
static __device__ __forceinline__ float2 upk(ull v) {
    float2 f;
    asm("mov.b64 {%0, %1}, %2;" : "=f"(f.x), "=f"(f.y) : "l"(v));
    return f;
}
static __device__ __forceinline__ float fsig(float x) {
    return __fdividef(1.0f, 1.0f + __expf(-x));
}
static __device__ __forceinline__ float ftanh(float x) {
    float e = __expf(2.0f * x);
    return 1.0f - __fdividef(2.0f, e + 1.0f);
}

// ---------------- lengths: count nonzero rows per batch ----------------
__global__ void lengths_kernel(const float* __restrict__ x, int* __restrict__ len) {
    const int b = blockIdx.x;
    const int warp = threadIdx.x >> 5, lane = threadIdx.x & 31;
    __shared__ int cnt;
    if (threadIdx.x == 0) cnt = 0;
    __syncthreads();
    int local = 0;
    for (int s = warp; s < Sv; s += 8) {
        const float2* row = (const float2*)(x + ((size_t)b * Sv + s) * Fv);
        float2 v = row[lane];
        bool nz = (v.x != 0.0f) || (v.y != 0.0f);
        if (__any_sync(0xffffffffu, nz)) local++;
    }
    if (lane == 0) atomicAdd(&cnt, local);
    __syncthreads();
    if (threadIdx.x == 0) len[b] = cnt;
}

// ---------------- stable-descending rank ----------------
__global__ void rank_kernel(const int* __restrict__ len, int* __restrict__ rank) {
    const int b = threadIdx.x;
    const int L = len[b];
    int r = 0;
    for (int j = 0; j < Bv; j++) {
        int Lj = len[j];
        r += (Lj > L) || (Lj == L && j < b);
    }
    rank[b] = r;
}

// ---------------- GEMM: C[m,n] = sum_k A[m,k]*W[n,k] + bias[n] ----------------
// Tile 128x128, BK=16, 128 threads, 16x8 per-thread microtile, f32x2 FMA.
__global__ void __launch_bounds__(128, 2) gemm_nt_bias(
    const float* __restrict__ A, const float* __restrict__ W,
    const float* __restrict__ bias, float* __restrict__ C,
    int K, int N)
{
    __shared__ __align__(16) float As[2][16][128];
    __shared__ __align__(16) float Ws[2][16][128];

    const int tid = threadIdx.x;
    const int m0 = blockIdx.x * 128;
    const int n0 = blockIdx.y * 128;
    const int tx = tid & 15;     // n micro-tile index (8 cols each)
    const int ty = tid >> 4;     // m micro-tile index (16 rows each)

    const float* Ap  = A + (size_t)(m0 + tid) * K;
    const float* Wpg = W + (size_t)(n0 + tid) * K;

    ull acc[8][8];
#pragma unroll
    for (int i = 0; i < 8; i++)
#pragma unroll
        for (int j = 0; j < 8; j++) acc[i][j] = 0ull;

    const int nst = K >> 4;
    float4 ra[4], rw[4];
#pragma unroll
    for (int j = 0; j < 4; j++) {
        ra[j] = *(const float4*)(Ap + 4 * j);
        rw[j] = *(const float4*)(Wpg + 4 * j);
    }

    auto sts = [&](int buf) {
#pragma unroll
        for (int j = 0; j < 4; j++) {
            As[buf][4 * j + 0][tid] = ra[j].x;
            As[buf][4 * j + 1][tid] = ra[j].y;
            As[buf][4 * j + 2][tid] = ra[j].z;
            As[buf][4 * j + 3][tid] = ra[j].w;
            Ws[buf][4 * j + 0][tid] = rw[j].x;
            Ws[buf][4 * j + 1][tid] = rw[j].y;
            Ws[buf][4 * j + 2][tid] = rw[j].z;
            Ws[buf][4 * j + 3][tid] = rw[j].w;
        }
    };

    sts(0);
    __syncthreads();

    for (int ks = 0; ks < nst; ks++) {
        const int cur = ks & 1;
        if (ks + 1 < nst) {
            const float* a2 = Ap + (ks + 1) * 16;
            const float* w2 = Wpg + (ks + 1) * 16;
#pragma unroll
            for (int j = 0; j < 4; j++) {
                ra[j] = *(const float4*)(a2 + 4 * j);
                rw[j] = *(const float4*)(w2 + 4 * j);
            }
        }
#pragma unroll
        for (int k = 0; k < 16; k++) {
            const float4* arow = (const float4*)&As[cur][k][ty * 16];
            float4 a0 = arow[0], a1 = arow[1], a2 = arow[2], a3 = arow[3];
            ull ap[8];
            ap[0] = pk2(a0.x, a0.y); ap[1] = pk2(a0.z, a0.w);
            ap[2] = pk2(a1.x, a1.y); ap[3] = pk2(a1.z, a1.w);
            ap[4] = pk2(a2.x, a2.y); ap[5] = pk2(a2.z, a2.w);
            ap[6] = pk2(a3.x, a3.y); ap[7] = pk2(a3.z, a3.w);
            const float4* brow = (const float4*)&Ws[cur][k][tx * 8];
            float4 b0 = brow[0], b1 = brow[1];
            ull bd[8];
            bd[0] = dup2(b0.x); bd[1] = dup2(b0.y);
            bd[2] = dup2(b0.z); bd[3] = dup2(b0.w);
            bd[4] = dup2(b1.x); bd[5] = dup2(b1.y);
            bd[6] = dup2(b1.z); bd[7] = dup2(b1.w);
#pragma unroll
            for (int i = 0; i < 8; i++)
#pragma unroll
                for (int j = 0; j < 8; j++)
                    fma2p(acc[i][j], ap[i], bd[j]);
        }
        if (ks + 1 < nst) {
            sts(cur ^ 1);
            __syncthreads();
        }
    }

    float bs[8];
#pragma unroll
    for (int j = 0; j < 8; j++) bs[j] = bias[n0 + tx * 8 + j];
#pragma unroll
    for (int i = 0; i < 8; i++) {
        float2 p[8];
#pragma unroll
        for (int j = 0; j < 8; j++) p[j] = upk(acc[i][j]);
        float* cp0 = C + (size_t)(m0 + ty * 16 + 2 * i) * N + n0 + tx * 8;
        float* cp1 = cp0 + N;
        float4 e0 = make_float4(p[0].x + bs[0], p[1].x + bs[1], p[2].x + bs[2], p[3].x + bs[3]);
        float4 e1 = make_float4(p[4].x + bs[4], p[5].x + bs[5], p[6].x + bs[6], p[7].x + bs[7]);
        float4 o0 = make_float4(p[0].y + bs[0], p[1].y + bs[1], p[2].y + bs[2], p[3].y + bs[3]);
        float4 o1 = make_float4(p[4].y + bs[4], p[5].y + bs[5], p[6].y + bs[6], p[7].y + bs[7]);
        *(float4*)cp0 = e0;
        *(float4*)(cp0 + 4) = e1;
        *(float4*)cp1 = o0;
        *(float4*)(cp1 + 4) = o1;
    }
}

// ---------------- GRU recurrence: one CTA per sequence ----------------
// 384 threads; thread g owns Whh[g,0:128] in regs (64 f32x2).
// Dot uses 8 accumulator chains (8-deep) + f32x2 tree reduce.
// xg prefetched through a 4-deep register ring (load->use slack ~3.5 steps).
// r/z rows fold xg into the dot bias; n rows pass xn via smem (needed
// outside the r*hn product).
template <bool LAST>
__global__ void __launch_bounds__(384, 1) gru_layer_kernel(
    const float* __restrict__ xg,   // [Bv,Sv,3H]
    const float* __restrict__ Whh,  // [3H,H]
    const float* __restrict__ bhh,  // [3H]
    const int* __restrict__ len,
    float* __restrict__ h_out,      // [Bv,Sv,H] when !LAST
    float* __restrict__ out,        // [Bv,H] when LAST (sorted order)
    const int* __restrict__ rank)
{
    const int b = blockIdx.x;
    const int g = threadIdx.x;

    __shared__ __align__(16) float h_sh[Hv];
    __shared__ float hg_sh[G3];
    __shared__ float xn_sh[Hv];

    ull w[64];
    {
        const float4* wp = (const float4*)(Whh + (size_t)g * Hv);
#pragma unroll
        for (int i = 0; i < 32; i++) {
            float4 v = wp[i];
            w[2 * i]     = pk2(v.x, v.y);
            w[2 * i + 1] = pk2(v.z, v.w);
        }
    }
    const float bh = bhh[g];
    const int L = len[b];
    const float* xb = xg + (size_t)b * Sv * G3 + g;
    const bool is_n_row = (g >= 2 * Hv);

    if (g < Hv) h_sh[g] = 0.0f;

    // 4-deep prefetch ring
    float xr[4];
#pragma unroll
    for (int j = 0; j < 4; j++)
        xr[j] = (j < L) ? xb[(size_t)j * G3] : 0.0f;
    const float* xpre = xb + (size_t)4 * G3;
    __syncthreads();

    float oacc = 0.0f;

    for (int s = 0; s < L; s++) {
        const int slot = s & 3;
        const float x0 = xr[slot];
        float xnew = 0.0f;
        if (s + 4 < L) xnew = *xpre;
        xpre += G3;

        // 8-chain dot: hg[g] = bias_eff + h . Whh[g,:]
        ull acc[8];
        acc[0] = pk2(is_n_row ? bh : (bh + x0), 0.0f);
#pragma unroll
        for (int c = 1; c < 8; c++) acc[c] = 0ull;
        const ulonglong2* hp = (const ulonglong2*)h_sh;
#pragma unroll
        for (int i = 0; i < 32; i++) {
            ulonglong2 hv = hp[i];
            fma2p(acc[(2 * i) & 7],     w[2 * i],     hv.x);
            fma2p(acc[(2 * i + 1) & 7], w[2 * i + 1], hv.y);
        }
        ull t0 = add2(acc[0], acc[1]);
        ull t1 = add2(acc[2], acc[3]);
        ull t2 = add2(acc[4], acc[5]);
        ull t3 = add2(acc[6], acc[7]);
        ull u0 = add2(t0, t1);
        ull u1 = add2(t2, t3);
        float2 v = upk(add2(u0, u1));
        if (is_n_row) xn_sh[g - 2 * Hv] = x0;
        hg_sh[g] = v.x + v.y;
        xr[slot] = xnew;
        __syncthreads();

        if (g < Hv) {
            float r = fsig(hg_sh[g]);
            float z = fsig(hg_sh[g + Hv]);
            float n = ftanh(xn_sh[g] + r * hg_sh[g + 2 * Hv]);
            float hprev = h_sh[g];
            float hnew = n + z * (hprev - n);
            h_sh[g] = hnew;
            if (!LAST) {
                h_out[((size_t)b * Sv + s) * Hv + g] = hnew;
            } else {
                oacc += hnew;
            }
        }
        __syncthreads();
    }

    if (LAST && g < Hv) {
        out[(size_t)rank[b] * Hv + g] = oacc * (1.0f / (float)Sv);
    }
}

// ---------------- launch ----------------
extern "C" void kernel_launch(void* const* d_in, const int* in_sizes, int n_in,
                              void* d_out, int out_size) {
    (void)in_sizes; (void)n_in; (void)out_size;
    const float* x    = (const float*)d_in[0];
    const float* Wp   = (const float*)d_in[1];
    const float* bp   = (const float*)d_in[2];
    const float* Wih0 = (const float*)d_in[3];
    const float* Whh0 = (const float*)d_in[4];
    const float* bih0 = (const float*)d_in[5];
    const float* bhh0 = (const float*)d_in[6];
    const float* Wih1 = (const float*)d_in[7];
    const float* Whh1 = (const float*)d_in[8];
    const float* bih1 = (const float*)d_in[9];
    const float* bhh1 = (const float*)d_in[10];
    float* out = (float*)d_out;

    float *xg, *proj;
    int *len, *rank;
    cudaGetSymbolAddress((void**)&xg, g_xg);
    cudaGetSymbolAddress((void**)&proj, g_proj);
    cudaGetSymbolAddress((void**)&len, g_len);
    cudaGetSymbolAddress((void**)&rank, g_rank);

    const int M = Bv * Sv;

    lengths_kernel<<<Bv, 256>>>(x, len);
    rank_kernel<<<1, Bv>>>(len, rank);
    // proj = x @ Wp^T + bp        [M,512] x [128,512] -> [M,128]
    gemm_nt_bias<<<dim3(M / 128, Hv / 128), 128>>>(x, Wp, bp, proj, Fv, Hv);
    // xg0 = proj @ Wih0^T + bih0  [M,128] x [384,128] -> [M,384]
    gemm_nt_bias<<<dim3(M / 128, G3 / 128), 128>>>(proj, Wih0, bih0, xg, Hv, G3);
    // layer 0 recurrence: writes h1 into proj buffer (proj no longer needed)
    gru_layer_kernel<false><<<Bv, 384>>>(xg, Whh0, bhh0, len, proj, nullptr, nullptr);
    // xg1 = h1 @ Wih1^T + bih1
    gemm_nt_bias<<<dim3(M / 128, G3 / 128), 128>>>(proj, Wih1, bih1, xg, Hv, G3);
    // layer 1 recurrence: accumulates masked mean, scatters by rank
    gru_layer_kernel<true><<<Bv, 384>>>(xg, Whh1, bhh1, len, nullptr, out, rank);
}

// round 5
// speedup vs baseline: 1.4237x; 1.4237x over previous
#include <cuda_runtime.h>
#include <cuda_bf16.h>
#include <cstdint>

#define Bv 128
#define Sv 1024
#define Fv 512
#define Hv 128
#define G3 (3*Hv)
#define STR 40   // smem row stride in bf16 elems (32 data + 8 pad)

typedef unsigned long long ull;

// ---------------- scratch (static device arrays; no allocation) ----------------
__device__ float g_xg[(size_t)Bv * Sv * G3];     // xg0, later reused for xg1
__device__ float g_proj[(size_t)Bv * Sv * Hv];   // proj, later reused for h1
__device__ int   g_len[Bv];
__device__ int   g_rank[Bv];

// ---------------- f32x2 helpers ----------------
static __device__ __forceinline__ ull pk2(float x, float y) {
    ull r;
    asm("mov.b64 %0, {%1, %2};" : "=l"(r) : "f"(x), "f"(y));
    return r;
}
static __device__ __forceinline__ void fma2p(ull &d, ull a, ull b) {
    asm("fma.rn.f32x2 %0, %1, %2, %0;" : "+l"(d) : "l"(a), "l"(b));
}
static __device__ __forceinline__ float2 upk(ull v) {
    float2 f;
    asm("mov.b64 {%0, %1}, %2;" : "=f"(f.x), "=f"(f.y) : "l"(v));
    return f;
}
static __device__ __forceinline__ float fsig(float x) {
    return __fdividef(1.0f, 1.0f + __expf(-x));
}
static __device__ __forceinline__ float ftanh(float x) {
    float e = __expf(2.0f * x);
    return 1.0f - __fdividef(2.0f, e + 1.0f);
}

// ---------------- mma helpers ----------------
static __device__ __forceinline__ uint32_t smem_u32(const void* p) {
    uint32_t a;
    asm("{ .reg .u64 t; cvta.to.shared.u64 t, %1; cvt.u32.u64 %0, t; }" : "=r"(a) : "l"(p));
    return a;
}
static __device__ __forceinline__ void ldm4(uint32_t r[4], uint32_t a) {
    asm volatile("ldmatrix.sync.aligned.m8n8.x4.shared.b16 {%0,%1,%2,%3}, [%4];"
                 : "=r"(r[0]), "=r"(r[1]), "=r"(r[2]), "=r"(r[3]) : "r"(a));
}
static __device__ __forceinline__ void mma16816(float d[4], const uint32_t a[4], const uint32_t b[2]) {
    asm volatile(
        "mma.sync.aligned.m16n8k16.row.col.f32.bf16.bf16.f32 "
        "{%0,%1,%2,%3}, {%4,%5,%6,%7}, {%8,%9}, {%0,%1,%2,%3};"
        : "+f"(d[0]), "+f"(d[1]), "+f"(d[2]), "+f"(d[3])
        : "r"(a[0]), "r"(a[1]), "r"(a[2]), "r"(a[3]), "r"(b[0]), "r"(b[1]));
}
// convert 8 fp32 -> 4 bf16x2 hi words + 4 lo (residual) words, store as uint4
static __device__ __forceinline__ void cvt_store(uint16_t* dst_hi, uint16_t* dst_lo,
                                                 const float f[8]) {
    uint32_t hw[4], lw[4];
#pragma unroll
    for (int j = 0; j < 4; j++) {
        float e0 = f[2 * j], e1 = f[2 * j + 1];
        uint32_t h;
        asm("cvt.rn.bf16x2.f32 %0, %1, %2;" : "=r"(h) : "f"(e1), "f"(e0)); // lo=e0, hi=e1
        float h0 = __uint_as_float(h << 16);
        float h1 = __uint_as_float(h & 0xffff0000u);
        float l0 = e0 - h0, l1 = e1 - h1;  // exact (Sterbenz)
        uint32_t l;
        asm("cvt.rn.bf16x2.f32 %0, %1, %2;" : "=r"(l) : "f"(l1), "f"(l0));
        hw[j] = h; lw[j] = l;
    }
    *(uint4*)dst_hi = make_uint4(hw[0], hw[1], hw[2], hw[3]);
    *(uint4*)dst_lo = make_uint4(lw[0], lw[1], lw[2], lw[3]);
}

// ---------------- tensor-core GEMM: C[m,n] = A[m,:K].W[n,:K] + bias[n] ----------------
// grid = (M/128, N/128); 512 threads; K multiple of 32.
// bf16 3-split: D = Ah.Wh + Al.Wh + Ah.Wl  (residual ~2^-18)
__global__ void __launch_bounds__(512, 1) gemm_mma(
    const float* __restrict__ A, const float* __restrict__ W,
    const float* __restrict__ bias, float* __restrict__ C,
    int K, int N)
{
    __shared__ __align__(16) uint16_t sAh[128 * STR];
    __shared__ __align__(16) uint16_t sAl[128 * STR];
    __shared__ __align__(16) uint16_t sWh[128 * STR];
    __shared__ __align__(16) uint16_t sWl[128 * STR];

    const int tid = threadIdx.x, lane = tid & 31, wid = tid >> 5;
    const int wm = wid & 3, wn = wid >> 2;           // warp tile = 32x32 at (wm*32, wn*32)
    const int m0 = blockIdx.x * 128, n0 = blockIdx.y * 128;

    // staging: thread -> (row 0..127, col-group 0..3 of 8 cols)
    const int srow = tid >> 2, scg = tid & 3;
    const float* Ag = A + (size_t)(m0 + srow) * K + scg * 8;
    const float* Wg = W + (size_t)(n0 + srow) * K + scg * 8;
    const int selem = srow * STR + scg * 8;

    const uint32_t uAh = smem_u32(sAh), uAl = smem_u32(sAl);
    const uint32_t uWh = smem_u32(sWh), uWl = smem_u32(sWl);

    // ldmatrix lane-address components (element offsets)
    const int a_r = lane & 15;
    const int a_c = (lane >> 4) << 3;
    const int b_r = (lane & 7) + ((lane >> 4) << 3);
    const int b_c = ((lane >> 3) & 1) << 3;

    float acc[2][4][4];
#pragma unroll
    for (int i = 0; i < 2; i++)
#pragma unroll
        for (int j = 0; j < 4; j++)
#pragma unroll
            for (int q = 0; q < 4; q++) acc[i][j][q] = 0.0f;

    const int nch = K >> 5;
    float fa[8], fw[8];
    {
        const float4* pa = (const float4*)Ag;
        const float4* pw = (const float4*)Wg;
        float4 v0 = pa[0], v1 = pa[1];
        fa[0]=v0.x; fa[1]=v0.y; fa[2]=v0.z; fa[3]=v0.w;
        fa[4]=v1.x; fa[5]=v1.y; fa[6]=v1.z; fa[7]=v1.w;
        float4 u0 = pw[0], u1 = pw[1];
        fw[0]=u0.x; fw[1]=u0.y; fw[2]=u0.z; fw[3]=u0.w;
        fw[4]=u1.x; fw[5]=u1.y; fw[6]=u1.z; fw[7]=u1.w;
    }

    for (int c = 0; c < nch; c++) {
        cvt_store(sAh + selem, sAl + selem, fa);
        cvt_store(sWh + selem, sWl + selem, fw);
        __syncthreads();

        if (c + 1 < nch) {
            const float4* pa = (const float4*)(Ag + (c + 1) * 32);
            const float4* pw = (const float4*)(Wg + (c + 1) * 32);
            float4 v0 = pa[0], v1 = pa[1];
            fa[0]=v0.x; fa[1]=v0.y; fa[2]=v0.z; fa[3]=v0.w;
            fa[4]=v1.x; fa[5]=v1.y; fa[6]=v1.z; fa[7]=v1.w;
            float4 u0 = pw[0], u1 = pw[1];
            fw[0]=u0.x; fw[1]=u0.y; fw[2]=u0.z; fw[3]=u0.w;
            fw[4]=u1.x; fw[5]=u1.y; fw[6]=u1.z; fw[7]=u1.w;
        }

#pragma unroll
        for (int kb = 0; kb < 32; kb += 16) {
            uint32_t ah[2][4], al[2][4];
#pragma unroll
            for (int mf = 0; mf < 2; mf++) {
                uint32_t off = ((uint32_t)(wm * 32 + mf * 16 + a_r) * STR + kb + a_c) * 2;
                ldm4(ah[mf], uAh + off);
                ldm4(al[mf], uAl + off);
            }
            uint32_t bh[2][4], bl[2][4];
#pragma unroll
            for (int nf2 = 0; nf2 < 2; nf2++) {
                uint32_t off = ((uint32_t)(wn * 32 + nf2 * 16 + b_r) * STR + kb + b_c) * 2;
                ldm4(bh[nf2], uWh + off);
                ldm4(bl[nf2], uWl + off);
            }
#pragma unroll
            for (int mf = 0; mf < 2; mf++)
#pragma unroll
                for (int nf = 0; nf < 4; nf++) {
                    const uint32_t* bfh = &bh[nf >> 1][(nf & 1) * 2];
                    const uint32_t* bfl = &bl[nf >> 1][(nf & 1) * 2];
                    mma16816(acc[mf][nf], ah[mf], bfh);
                    mma16816(acc[mf][nf], al[mf], bfh);
                    mma16816(acc[mf][nf], ah[mf], bfl);
                }
        }
        __syncthreads();
    }

    // epilogue: warp covers rows [wm*32, +32), cols [wn*32, +32)
    const int erow = wm * 32 + (lane >> 2);
    const int ecol = wn * 32 + 2 * (lane & 3);
#pragma unroll
    for (int mf = 0; mf < 2; mf++) {
#pragma unroll
        for (int nf = 0; nf < 4; nf++) {
            int r = m0 + erow + mf * 16;
            int col = n0 + ecol + nf * 8;
            float b0 = bias[col], b1 = bias[col + 1];
            float2 v0 = make_float2(acc[mf][nf][0] + b0, acc[mf][nf][1] + b1);
            float2 v1 = make_float2(acc[mf][nf][2] + b0, acc[mf][nf][3] + b1);
            *(float2*)(C + (size_t)r * N + col) = v0;
            *(float2*)(C + (size_t)(r + 8) * N + col) = v1;
        }
    }
}

// ---------------- lengths: count nonzero rows per batch ----------------
__global__ void lengths_kernel(const float* __restrict__ x, int* __restrict__ len) {
    const int b = blockIdx.x;
    const int warp = threadIdx.x >> 5, lane = threadIdx.x & 31;
    __shared__ int cnt;
    if (threadIdx.x == 0) cnt = 0;
    __syncthreads();
    int local = 0;
    for (int s = warp; s < Sv; s += 8) {
        const float2* row = (const float2*)(x + ((size_t)b * Sv + s) * Fv);
        float2 v = row[lane];
        bool nz = (v.x != 0.0f) || (v.y != 0.0f);
        if (__any_sync(0xffffffffu, nz)) local++;
    }
    if (lane == 0) atomicAdd(&cnt, local);
    __syncthreads();
    if (threadIdx.x == 0) len[b] = cnt;
}

// ---------------- stable-descending rank ----------------
__global__ void rank_kernel(const int* __restrict__ len, int* __restrict__ rank) {
    const int b = threadIdx.x;
    const int L = len[b];
    int r = 0;
    for (int j = 0; j < Bv; j++) {
        int Lj = len[j];
        r += (Lj > L) || (Lj == L && j < b);
    }
    rank[b] = r;
}

// ---------------- GRU recurrence (R2 version): one CTA per sequence ----------------
template <bool LAST>
__global__ void __launch_bounds__(384, 1) gru_layer_kernel(
    const float* __restrict__ xg,   // [Bv,Sv,3H]
    const float* __restrict__ Whh,  // [3H,H]
    const float* __restrict__ bhh,  // [3H]
    const int* __restrict__ len,
    float* __restrict__ h_out,      // [Bv,Sv,H] when !LAST
    float* __restrict__ out,        // [Bv,H] when LAST (sorted order)
    const int* __restrict__ rank)
{
    const int b = blockIdx.x;
    const int g = threadIdx.x;

    __shared__ __align__(16) float h_sh[Hv];
    __shared__ float hg_sh[G3];
    __shared__ float xn_sh[Hv];

    ull w[64];
    {
        const float4* wp = (const float4*)(Whh + (size_t)g * Hv);
#pragma unroll
        for (int i = 0; i < 32; i++) {
            float4 v = wp[i];
            w[2 * i]     = pk2(v.x, v.y);
            w[2 * i + 1] = pk2(v.z, v.w);
        }
    }
    const float bh = bhh[g];
    const int L = len[b];
    const float* xb = xg + (size_t)b * Sv * G3 + g;
    const bool is_n_row = (g >= 2 * Hv);

    if (g < Hv) h_sh[g] = 0.0f;
    float x0 = (L > 0) ? xb[0] : 0.0f;
    float x1 = (L > 1) ? xb[G3] : 0.0f;
    __syncthreads();

    float oacc = 0.0f;

    for (int s = 0; s < L; s++) {
        float xN = (s + 2 < L) ? xb[(size_t)(s + 2) * G3] : 0.0f;

        ull a0 = pk2(is_n_row ? bh : (bh + x0), 0.0f);
        ull a1 = 0ull;
        const ulonglong2* hp = (const ulonglong2*)h_sh;
#pragma unroll
        for (int i = 0; i < 32; i++) {
            ulonglong2 hv = hp[i];
            fma2p(a0, w[2 * i],     hv.x);
            fma2p(a1, w[2 * i + 1], hv.y);
        }
        float2 f0 = upk(a0), f1 = upk(a1);
        if (is_n_row) xn_sh[g - 2 * Hv] = x0;
        hg_sh[g] = (f0.x + f1.x) + (f0.y + f1.y);
        __syncthreads();

        if (g < Hv) {
            float r = fsig(hg_sh[g]);
            float z = fsig(hg_sh[g + Hv]);
            float n = ftanh(xn_sh[g] + r * hg_sh[g + 2 * Hv]);
            float hprev = h_sh[g];
            float hnew = n + z * (hprev - n);
            h_sh[g] = hnew;
            if (!LAST) {
                h_out[((size_t)b * Sv + s) * Hv + g] = hnew;
            } else {
                oacc += hnew;
            }
        }
        __syncthreads();
        x0 = x1;
        x1 = xN;
    }

    if (LAST && g < Hv) {
        out[(size_t)rank[b] * Hv + g] = oacc * (1.0f / (float)Sv);
    }
}

// ---------------- launch ----------------
extern "C" void kernel_launch(void* const* d_in, const int* in_sizes, int n_in,
                              void* d_out, int out_size) {
    (void)in_sizes; (void)n_in; (void)out_size;
    const float* x    = (const float*)d_in[0];
    const float* Wp   = (const float*)d_in[1];
    const float* bp   = (const float*)d_in[2];
    const float* Wih0 = (const float*)d_in[3];
    const float* Whh0 = (const float*)d_in[4];
    const float* bih0 = (const float*)d_in[5];
    const float* bhh0 = (const float*)d_in[6];
    const float* Wih1 = (const float*)d_in[7];
    const float* Whh1 = (const float*)d_in[8];
    const float* bih1 = (const float*)d_in[9];
    const float* bhh1 = (const float*)d_in[10];
    float* out = (float*)d_out;

    float *xg, *proj;
    int *len, *rank;
    cudaGetSymbolAddress((void**)&xg, g_xg);
    cudaGetSymbolAddress((void**)&proj, g_proj);
    cudaGetSymbolAddress((void**)&len, g_len);
    cudaGetSymbolAddress((void**)&rank, g_rank);

    const int M = Bv * Sv;

    lengths_kernel<<<Bv, 256>>>(x, len);
    rank_kernel<<<1, Bv>>>(len, rank);
    // proj = x @ Wp^T + bp        [M,512] x [128,512] -> [M,128]
    gemm_mma<<<dim3(M / 128, 1), 512>>>(x, Wp, bp, proj, Fv, Hv);
    // xg0 = proj @ Wih0^T + bih0  [M,128] x [384,128] -> [M,384]
    gemm_mma<<<dim3(M / 128, 3), 512>>>(proj, Wih0, bih0, xg, Hv, G3);
    // layer 0 recurrence: writes h1 into proj buffer (proj no longer needed)
    gru_layer_kernel<false><<<Bv, 384>>>(xg, Whh0, bhh0, len, proj, nullptr, nullptr);
    // xg1 = h1 @ Wih1^T + bih1
    gemm_mma<<<dim3(M / 128, 3), 512>>>(proj, Wih1, bih1, xg, Hv, G3);
    // layer 1 recurrence: accumulates masked mean, scatters by rank
    gru_layer_kernel<true><<<Bv, 384>>>(xg, Whh1, bhh1, len, nullptr, out, rank);
}

// round 6
// speedup vs baseline: 1.4702x; 1.0327x over previous
#include <cuda_runtime.h>
#include <cuda_bf16.h>
#include <cstdint>

#define Bv 128
#define Sv 1024
#define Fv 512
#define Hv 128
#define G3 (3*Hv)
#define STR 40   // smem row stride in bf16 elems (32 data + 8 pad)

typedef unsigned long long ull;

// ---------------- scratch (static device arrays; no allocation) ----------------
__device__ float g_xg[(size_t)Bv * Sv * G3];     // xg0, later reused for xg1
__device__ float g_proj[(size_t)Bv * Sv * Hv];   // proj, later reused for h1
__device__ int   g_len[Bv];
__device__ int   g_rank[Bv];

// ---------------- f32x2 helpers ----------------
static __device__ __forceinline__ ull pk2(float x, float y) {
    ull r;
    asm("mov.b64 %0, {%1, %2};" : "=l"(r) : "f"(x), "f"(y));
    return r;
}
static __device__ __forceinline__ void fma2p(ull &d, ull a, ull b) {
    asm("fma.rn.f32x2 %0, %1, %2, %0;" : "+l"(d) : "l"(a), "l"(b));
}
static __device__ __forceinline__ float2 upk(ull v) {
    float2 f;
    asm("mov.b64 {%0, %1}, %2;" : "=f"(f.x), "=f"(f.y) : "l"(v));
    return f;
}
static __device__ __forceinline__ float fsig(float x) {
    return __fdividef(1.0f, 1.0f + __expf(-x));
}
static __device__ __forceinline__ float ftanh(float x) {
    float e = __expf(2.0f * x);
    return 1.0f - __fdividef(2.0f, e + 1.0f);
}

// ---------------- mma helpers ----------------
static __device__ __forceinline__ uint32_t smem_u32(const void* p) {
    uint32_t a;
    asm("{ .reg .u64 t; cvta.to.shared.u64 t, %1; cvt.u32.u64 %0, t; }" : "=r"(a) : "l"(p));
    return a;
}
static __device__ __forceinline__ void ldm4(uint32_t r[4], uint32_t a) {
    asm volatile("ldmatrix.sync.aligned.m8n8.x4.shared.b16 {%0,%1,%2,%3}, [%4];"
                 : "=r"(r[0]), "=r"(r[1]), "=r"(r[2]), "=r"(r[3]) : "r"(a));
}
static __device__ __forceinline__ void mma16816(float d[4], const uint32_t a[4], const uint32_t b[2]) {
    asm volatile(
        "mma.sync.aligned.m16n8k16.row.col.f32.bf16.bf16.f32 "
        "{%0,%1,%2,%3}, {%4,%5,%6,%7}, {%8,%9}, {%0,%1,%2,%3};"
        : "+f"(d[0]), "+f"(d[1]), "+f"(d[2]), "+f"(d[3])
        : "r"(a[0]), "r"(a[1]), "r"(a[2]), "r"(a[3]), "r"(b[0]), "r"(b[1]));
}
// convert 8 fp32 -> 4 bf16x2 hi words + 4 lo (residual) words, store as uint4
static __device__ __forceinline__ void cvt_store(uint16_t* dst_hi, uint16_t* dst_lo,
                                                 const float f[8]) {
    uint32_t hw[4], lw[4];
#pragma unroll
    for (int j = 0; j < 4; j++) {
        float e0 = f[2 * j], e1 = f[2 * j + 1];
        uint32_t h;
        asm("cvt.rn.bf16x2.f32 %0, %1, %2;" : "=r"(h) : "f"(e1), "f"(e0)); // lo=e0, hi=e1
        float h0 = __uint_as_float(h << 16);
        float h1 = __uint_as_float(h & 0xffff0000u);
        float l0 = e0 - h0, l1 = e1 - h1;  // exact (Sterbenz)
        uint32_t l;
        asm("cvt.rn.bf16x2.f32 %0, %1, %2;" : "=r"(l) : "f"(l1), "f"(l0));
        hw[j] = h; lw[j] = l;
    }
    *(uint4*)dst_hi = make_uint4(hw[0], hw[1], hw[2], hw[3]);
    *(uint4*)dst_lo = make_uint4(lw[0], lw[1], lw[2], lw[3]);
}

// ---------------- tensor-core GEMM: C[m,n] = A[m,:K].W[n,:K] + bias[n] ----------------
// grid = (M/128, N/128); 512 threads; K multiple of 32.
// bf16 3-split: D = Ah.Wh + Al.Wh + Ah.Wl  (residual ~2^-18)
__global__ void __launch_bounds__(512, 1) gemm_mma(
    const float* __restrict__ A, const float* __restrict__ W,
    const float* __restrict__ bias, float* __restrict__ C,
    int K, int N)
{
    __shared__ __align__(16) uint16_t sAh[128 * STR];
    __shared__ __align__(16) uint16_t sAl[128 * STR];
    __shared__ __align__(16) uint16_t sWh[128 * STR];
    __shared__ __align__(16) uint16_t sWl[128 * STR];

    const int tid = threadIdx.x, lane = tid & 31, wid = tid >> 5;
    const int wm = wid & 3, wn = wid >> 2;           // warp tile = 32x32 at (wm*32, wn*32)
    const int m0 = blockIdx.x * 128, n0 = blockIdx.y * 128;

    // staging: thread -> (row 0..127, col-group 0..3 of 8 cols)
    const int srow = tid >> 2, scg = tid & 3;
    const float* Ag = A + (size_t)(m0 + srow) * K + scg * 8;
    const float* Wg = W + (size_t)(n0 + srow) * K + scg * 8;
    const int selem = srow * STR + scg * 8;

    const uint32_t uAh = smem_u32(sAh), uAl = smem_u32(sAl);
    const uint32_t uWh = smem_u32(sWh), uWl = smem_u32(sWl);

    // ldmatrix lane-address components (element offsets)
    const int a_r = lane & 15;
    const int a_c = (lane >> 4) << 3;
    const int b_r = (lane & 7) + ((lane >> 4) << 3);
    const int b_c = ((lane >> 3) & 1) << 3;

    float acc[2][4][4];
#pragma unroll
    for (int i = 0; i < 2; i++)
#pragma unroll
        for (int j = 0; j < 4; j++)
#pragma unroll
            for (int q = 0; q < 4; q++) acc[i][j][q] = 0.0f;

    const int nch = K >> 5;
    float fa[8], fw[8];
    {
        const float4* pa = (const float4*)Ag;
        const float4* pw = (const float4*)Wg;
        float4 v0 = pa[0], v1 = pa[1];
        fa[0]=v0.x; fa[1]=v0.y; fa[2]=v0.z; fa[3]=v0.w;
        fa[4]=v1.x; fa[5]=v1.y; fa[6]=v1.z; fa[7]=v1.w;
        float4 u0 = pw[0], u1 = pw[1];
        fw[0]=u0.x; fw[1]=u0.y; fw[2]=u0.z; fw[3]=u0.w;
        fw[4]=u1.x; fw[5]=u1.y; fw[6]=u1.z; fw[7]=u1.w;
    }

    for (int c = 0; c < nch; c++) {
        cvt_store(sAh + selem, sAl + selem, fa);
        cvt_store(sWh + selem, sWl + selem, fw);
        __syncthreads();

        if (c + 1 < nch) {
            const float4* pa = (const float4*)(Ag + (c + 1) * 32);
            const float4* pw = (const float4*)(Wg + (c + 1) * 32);
            float4 v0 = pa[0], v1 = pa[1];
            fa[0]=v0.x; fa[1]=v0.y; fa[2]=v0.z; fa[3]=v0.w;
            fa[4]=v1.x; fa[5]=v1.y; fa[6]=v1.z; fa[7]=v1.w;
            float4 u0 = pw[0], u1 = pw[1];
            fw[0]=u0.x; fw[1]=u0.y; fw[2]=u0.z; fw[3]=u0.w;
            fw[4]=u1.x; fw[5]=u1.y; fw[6]=u1.z; fw[7]=u1.w;
        }

#pragma unroll
        for (int kb = 0; kb < 32; kb += 16) {
            uint32_t ah[2][4], al[2][4];
#pragma unroll
            for (int mf = 0; mf < 2; mf++) {
                uint32_t off = ((uint32_t)(wm * 32 + mf * 16 + a_r) * STR + kb + a_c) * 2;
                ldm4(ah[mf], uAh + off);
                ldm4(al[mf], uAl + off);
            }
            uint32_t bh[2][4], bl[2][4];
#pragma unroll
            for (int nf2 = 0; nf2 < 2; nf2++) {
                uint32_t off = ((uint32_t)(wn * 32 + nf2 * 16 + b_r) * STR + kb + b_c) * 2;
                ldm4(bh[nf2], uWh + off);
                ldm4(bl[nf2], uWl + off);
            }
#pragma unroll
            for (int mf = 0; mf < 2; mf++)
#pragma unroll
                for (int nf = 0; nf < 4; nf++) {
                    const uint32_t* bfh = &bh[nf >> 1][(nf & 1) * 2];
                    const uint32_t* bfl = &bl[nf >> 1][(nf & 1) * 2];
                    mma16816(acc[mf][nf], ah[mf], bfh);
                    mma16816(acc[mf][nf], al[mf], bfh);
                    mma16816(acc[mf][nf], ah[mf], bfl);
                }
        }
        __syncthreads();
    }

    // epilogue: warp covers rows [wm*32, +32), cols [wn*32, +32)
    const int erow = wm * 32 + (lane >> 2);
    const int ecol = wn * 32 + 2 * (lane & 3);
#pragma unroll
    for (int mf = 0; mf < 2; mf++) {
#pragma unroll
        for (int nf = 0; nf < 4; nf++) {
            int r = m0 + erow + mf * 16;
            int col = n0 + ecol + nf * 8;
            float b0 = bias[col], b1 = bias[col + 1];
            float2 v0 = make_float2(acc[mf][nf][0] + b0, acc[mf][nf][1] + b1);
            float2 v1 = make_float2(acc[mf][nf][2] + b0, acc[mf][nf][3] + b1);
            *(float2*)(C + (size_t)r * N + col) = v0;
            *(float2*)(C + (size_t)(r + 8) * N + col) = v1;
        }
    }
}

// ---------------- lengths: count nonzero rows per batch ----------------
__global__ void lengths_kernel(const float* __restrict__ x, int* __restrict__ len) {
    const int b = blockIdx.x;
    const int warp = threadIdx.x >> 5, lane = threadIdx.x & 31;
    __shared__ int cnt;
    if (threadIdx.x == 0) cnt = 0;
    __syncthreads();
    int local = 0;
    for (int s = warp; s < Sv; s += 8) {
        const float2* row = (const float2*)(x + ((size_t)b * Sv + s) * Fv);
        float2 v = row[lane];
        bool nz = (v.x != 0.0f) || (v.y != 0.0f);
        if (__any_sync(0xffffffffu, nz)) local++;
    }
    if (lane == 0) atomicAdd(&cnt, local);
    __syncthreads();
    if (threadIdx.x == 0) len[b] = cnt;
}

// ---------------- stable-descending rank ----------------
__global__ void rank_kernel(const int* __restrict__ len, int* __restrict__ rank) {
    const int b = threadIdx.x;
    const int L = len[b];
    int r = 0;
    for (int j = 0; j < Bv; j++) {
        int Lj = len[j];
        r += (Lj > L) || (Lj == L && j < b);
    }
    rank[b] = r;
}

// ---------------- GRU recurrence: one CTA per sequence ----------------
// 384 threads; thread g owns Whh[g,0:128] in regs (64 f32x2).
// Sigmoids moved into the dot phase (MUFU pipe is idle there and the work
// spreads over 8 warps instead of being 1-warp/SMSP throughput-bound):
//   r-rows store sigma(hg); z-rows store (1-z) and z*h_prev; n-rows store
//   raw hn and xn.  Combine phase: n = tanh(xn + r*hn); h = fma(n,1-z,zh).
template <bool LAST>
__global__ void __launch_bounds__(384, 1) gru_layer_kernel(
    const float* __restrict__ xg,   // [Bv,Sv,3H]
    const float* __restrict__ Whh,  // [3H,H]
    const float* __restrict__ bhh,  // [3H]
    const int* __restrict__ len,
    float* __restrict__ h_out,      // [Bv,Sv,H] when !LAST
    float* __restrict__ out,        // [Bv,H] when LAST (sorted order)
    const int* __restrict__ rank)
{
    const int b = blockIdx.x;
    const int g = threadIdx.x;

    __shared__ __align__(16) float h_sh[Hv];
    __shared__ float r_sh[Hv];
    __shared__ float omz_sh[Hv];   // 1 - z
    __shared__ float zh_sh[Hv];    // z * h_prev
    __shared__ float hn_sh[Hv];
    __shared__ float xn_sh[Hv];

    ull w[64];
    {
        const float4* wp = (const float4*)(Whh + (size_t)g * Hv);
#pragma unroll
        for (int i = 0; i < 32; i++) {
            float4 v = wp[i];
            w[2 * i]     = pk2(v.x, v.y);
            w[2 * i + 1] = pk2(v.z, v.w);
        }
    }
    const float bh = bhh[g];
    const int L = len[b];
    const float* xb = xg + (size_t)b * Sv * G3 + g;
    const int gate = g >> 7;        // 0 = r, 1 = z, 2 = n
    const int j = g & (Hv - 1);     // output index within gate

    if (g < Hv) h_sh[g] = 0.0f;
    float x0 = (L > 0) ? xb[0] : 0.0f;
    float x1 = (L > 1) ? xb[G3] : 0.0f;
    __syncthreads();

    float oacc = 0.0f;

    for (int s = 0; s < L; s++) {
        float xN = (s + 2 < L) ? xb[(size_t)(s + 2) * G3] : 0.0f;

        // dot: hg = bias_eff + h . Whh[g,:]   (x folded for r/z gates)
        ull a0 = pk2((gate == 2) ? bh : (bh + x0), 0.0f);
        ull a1 = 0ull;
        const ulonglong2* hp = (const ulonglong2*)h_sh;
#pragma unroll
        for (int i = 0; i < 32; i++) {
            ulonglong2 hv = hp[i];
            fma2p(a0, w[2 * i],     hv.x);
            fma2p(a1, w[2 * i + 1], hv.y);
        }
        float2 f0 = upk(a0), f1 = upk(a1);
        const float hg = (f0.x + f1.x) + (f0.y + f1.y);

        // gate-specific phase-A postprocessing (MUFU overlaps the fma phase
        // of other warps; pipes are disjoint)
        if (gate == 0) {
            r_sh[j] = fsig(hg);
        } else if (gate == 1) {
            float z = fsig(hg);
            omz_sh[j] = 1.0f - z;
            zh_sh[j] = z * h_sh[j];
        } else {
            hn_sh[j] = hg;
            xn_sh[j] = x0;
        }
        __syncthreads();

        // combine: only 128 threads, short MUFU chain (one tanh)
        if (g < Hv) {
            float n = ftanh(fmaf(r_sh[g], hn_sh[g], xn_sh[g]));
            float hnew = fmaf(n, omz_sh[g], zh_sh[g]);
            h_sh[g] = hnew;
            if (!LAST) {
                h_out[((size_t)b * Sv + s) * Hv + g] = hnew;
            } else {
                oacc += hnew;
            }
        }
        __syncthreads();
        x0 = x1;
        x1 = xN;
    }

    if (LAST && g < Hv) {
        out[(size_t)rank[b] * Hv + g] = oacc * (1.0f / (float)Sv);
    }
}

// ---------------- launch ----------------
extern "C" void kernel_launch(void* const* d_in, const int* in_sizes, int n_in,
                              void* d_out, int out_size) {
    (void)in_sizes; (void)n_in; (void)out_size;
    const float* x    = (const float*)d_in[0];
    const float* Wp   = (const float*)d_in[1];
    const float* bp   = (const float*)d_in[2];
    const float* Wih0 = (const float*)d_in[3];
    const float* Whh0 = (const float*)d_in[4];
    const float* bih0 = (const float*)d_in[5];
    const float* bhh0 = (const float*)d_in[6];
    const float* Wih1 = (const float*)d_in[7];
    const float* Whh1 = (const float*)d_in[8];
    const float* bih1 = (const float*)d_in[9];
    const float* bhh1 = (const float*)d_in[10];
    float* out = (float*)d_out;

    float *xg, *proj;
    int *len, *rank;
    cudaGetSymbolAddress((void**)&xg, g_xg);
    cudaGetSymbolAddress((void**)&proj, g_proj);
    cudaGetSymbolAddress((void**)&len, g_len);
    cudaGetSymbolAddress((void**)&rank, g_rank);

    const int M = Bv * Sv;

    lengths_kernel<<<Bv, 256>>>(x, len);
    rank_kernel<<<1, Bv>>>(len, rank);
    // proj = x @ Wp^T + bp        [M,512] x [128,512] -> [M,128]
    gemm_mma<<<dim3(M / 128, 1), 512>>>(x, Wp, bp, proj, Fv, Hv);
    // xg0 = proj @ Wih0^T + bih0  [M,128] x [384,128] -> [M,384]
    gemm_mma<<<dim3(M / 128, 3), 512>>>(proj, Wih0, bih0, xg, Hv, G3);
    // layer 0 recurrence: writes h1 into proj buffer (proj no longer needed)
    gru_layer_kernel<false><<<Bv, 384>>>(xg, Whh0, bhh0, len, proj, nullptr, nullptr);
    // xg1 = h1 @ Wih1^T + bih1
    gemm_mma<<<dim3(M / 128, 3), 512>>>(proj, Wih1, bih1, xg, Hv, G3);
    // layer 1 recurrence: accumulates masked mean, scatters by rank
    gru_layer_kernel<true><<<Bv, 384>>>(xg, Whh1, bhh1, len, nullptr, out, rank);
}